// round 17
// baseline (speedup 1.0000x reference)
#include <cuda_runtime.h>
#include <cuda_fp16.h>
#include <math.h>
#include <stdint.h>

#define TT     512
#define HH     64
#define DD     576
#define DV     512
#define NKV    8192
#define TOPK   1024
#define TILE   32
#define NTILES 32
#define HB     16                 // heads per block (grid.x = 4)
#define KSTRIDE 584               // halves per KV/Q smem row (1168 B)
#define ROWB   (KSTRIDE * 2)
#define CPROW  1152
#define PSTRIDE 40
#define KVBUF  (TILE * KSTRIDE)
#define SCALE_F (1.0f / 24.0f)
#define LOG2E   1.4426950408889634f
#define TILE_TX (TILE * CPROW)

// smem layout (bytes)
#define SP_OFFB    (2 * KVBUF * 2)                   // 74752 : sP [16][40] halves
#define SPART_OFFB (SP_OFFB + HB * PSTRIDE * 2)      // 76032 : sPart [2][4][4][32] float2
#define SLP_OFFB   (SPART_OFFB + 2*4*4*32*8)         // 84224 : sLp float[4][16]
#define SIDX_OFFB  (SLP_OFFB + 4*16*4)               // 84480 : sIdx int[2][32]
#define SMB_OFFB   (SIDX_OFFB + 2*32*4)              // 84736
#define SMEM_BYTES (SMB_OFFB + 64)

__device__ __align__(16) half g_kvh[(size_t)NKV * DD];

__global__ void __launch_bounds__(256)
kv_to_half_kernel(const float* __restrict__ kv)
{
    size_t i = (size_t)blockIdx.x * 256 + threadIdx.x;
    float4 v = ((const float4*)kv)[i];
    half2 a = __floats2half2_rn(v.x, v.y);
    half2 b = __floats2half2_rn(v.z, v.w);
    uint2 u; u.x = *(uint32_t*)&a; u.y = *(uint32_t*)&b;
    ((uint2*)g_kvh)[i] = u;
}

__device__ __forceinline__ void ldsm_x4(uint32_t& r0, uint32_t& r1, uint32_t& r2, uint32_t& r3, uint32_t a) {
    asm volatile("ldmatrix.sync.aligned.m8n8.x4.shared.b16 {%0,%1,%2,%3}, [%4];"
                 : "=r"(r0), "=r"(r1), "=r"(r2), "=r"(r3) : "r"(a));
}
__device__ __forceinline__ void ldsm_x4t(uint32_t& r0, uint32_t& r1, uint32_t& r2, uint32_t& r3, uint32_t a) {
    asm volatile("ldmatrix.sync.aligned.m8n8.x4.trans.shared.b16 {%0,%1,%2,%3}, [%4];"
                 : "=r"(r0), "=r"(r1), "=r"(r2), "=r"(r3) : "r"(a));
}
__device__ __forceinline__ void mma16816(float& d0, float& d1, float& d2, float& d3,
                                         uint32_t a0, uint32_t a1, uint32_t a2, uint32_t a3,
                                         uint32_t b0, uint32_t b1,
                                         float c0, float c1, float c2, float c3) {
    asm volatile("mma.sync.aligned.m16n8k16.row.col.f32.f16.f16.f32 "
                 "{%0,%1,%2,%3},{%4,%5,%6,%7},{%8,%9},{%10,%11,%12,%13};"
                 : "=f"(d0), "=f"(d1), "=f"(d2), "=f"(d3)
                 : "r"(a0), "r"(a1), "r"(a2), "r"(a3), "r"(b0), "r"(b1),
                   "f"(c0), "f"(c1), "f"(c2), "f"(c3));
}
#define MB_WAIT(mb, ph) do { \
    asm volatile("{\n .reg .pred P1;\n WL%=:\n" \
        " mbarrier.try_wait.parity.acquire.cta.shared::cta.b64 P1, [%0], %1, 0x989680;\n" \
        " @P1 bra.uni WD%=;\n bra.uni WL%=;\n WD%=:\n}" :: "r"(mb), "r"(ph) : "memory"); \
} while (0)

__global__ void __launch_bounds__(256, 2)
mla_v13_kernel(const float* __restrict__ q,     // [T,H,D]
               const int*   __restrict__ topk,  // [T,TOPK]
               const float* __restrict__ sink,  // [H]
               float*       __restrict__ out)   // [T,H,DV]
{
    extern __shared__ char smem_raw[];
    half*  sKVh  = (half*)smem_raw;                       // [2][KVBUF]
    half*  sP    = (half*)(smem_raw + SP_OFFB);           // [16][40]
    float* sPart = (float*)(smem_raw + SPART_OFFB);       // [2 nt][4 dst][4 src][32] float2
    float* sLp   = (float*)(smem_raw + SLP_OFFB);         // [4][16]
    int*   sIdx  = (int*)(smem_raw + SIDX_OFFB);          // [2][32]

    const int hblk = blockIdx.x;       // 0..3
    const int tok  = blockIdx.y;       // 0..511
    const int tid  = threadIdx.x;
    const int lt   = tid & 31;
    const int w    = tid >> 5;         // 8 warps
    const int nt   = w >> 2;           // token half (16 tokens)
    const int ks   = w & 3;            // k-split quarter; also combo owner (ntile, rowhalf)
    const int ntile   = ks & 1;        // which 8-token n-tile of the 16
    const int rowhalf = ks >> 1;       // head rows 0-7 vs 8-15

    const uint32_t skv0 = (uint32_t)__cvta_generic_to_shared(sKVh);
    const uint32_t spb  = (uint32_t)__cvta_generic_to_shared(sP);
    const uint32_t mbar = skv0 + SMB_OFFB;

    if (tid < 2) {
        asm volatile("mbarrier.init.shared.b64 [%0], 1;" :: "r"(mbar + tid * 8) : "memory");
    }

    // ---- stage Q (pre-scaled by 1/sqrt(D)*log2e) into sKV buf0 ----
    {
        const float qsc = SCALE_F * LOG2E;
        int h = tid >> 4, j = tid & 15;
        const float4* qs = (const float4*)(q + ((size_t)tok * HH + hblk * HB + h) * DD) + j;
        half* qd = sKVh + h * KSTRIDE;
        #pragma unroll
        for (int i = 0; i < 9; ++i) {
            float4 v = qs[i * 16];
            half2 h0 = __floats2half2_rn(v.x * qsc, v.y * qsc);
            half2 h1 = __floats2half2_rn(v.z * qsc, v.w * qsc);
            uint2 u; u.x = *(uint32_t*)&h0; u.y = *(uint32_t*)&h1;
            *(uint2*)(qd + (j + i * 16) * 4) = u;
        }
    }
    __syncthreads();

    // Q A-fragments for this warp's 144-dim slice: 9 k-steps (16 heads)
    uint32_t qf[36];
    {
        uint32_t qa = skv0 + (uint32_t)(((lt & 15) * KSTRIDE + ks * 144 + (lt >> 4) * 8) * 2);
        #pragma unroll
        for (int s = 0; s < 9; ++s) {
            ldsm_x4(qf[4*s], qf[4*s+1], qf[4*s+2], qf[4*s+3], qa);
            qa += 32;
        }
    }
    __syncthreads();   // Q frags read before gather overwrites buf0

    const int* tkp = topk + (size_t)tok * TOPK;

    // ---- bulk gather: warp 0, one row per lane ----
    auto gather = [&](int tile) {
        int buf = tile & 1;
        int raw = tkp[tile * TILE + lt];
        sIdx[buf * 32 + lt] = raw;
        int r2 = raw < 0 ? 0 : raw;
        if (lt == 0) {
            asm volatile("mbarrier.arrive.expect_tx.shared.b64 _, [%0], %1;"
                         :: "r"(mbar + buf * 8), "r"((uint32_t)TILE_TX) : "memory");
        }
        __syncwarp();
        uint32_t dst = skv0 + (uint32_t)(buf * (KVBUF * 2) + lt * ROWB);
        const half* src = g_kvh + (size_t)r2 * DD;
        asm volatile("cp.async.bulk.shared::cta.global.mbarrier::complete_tx::bytes [%0], [%1], %2, [%3];"
                     :: "r"(dst), "l"(src), "r"((uint32_t)CPROW), "r"(mbar + buf * 8) : "memory");
    };

    if (w == 0) gather(0);
    if (w == 0) MB_WAIT(mbar, 0);
    __syncthreads();

    // PV accumulator: [16h x 64d] per warp (d-range w*64)
    float accO[8][4];
    #pragma unroll
    for (int n = 0; n < 8; ++n)
        accO[n][0] = accO[n][1] = accO[n][2] = accO[n][3] = 0.0f;

    float rs = 0.0f;   // row-sum for head row rowhalf*8+(lt>>2), own token pairs

    const uint32_t qkB_off = (uint32_t)(((nt * 16 + (lt & 15)) * KSTRIDE + ks * 144 + (lt >> 4) * 8) * 2);
    const uint32_t pvB_off = (uint32_t)((lt * KSTRIDE + w * 64) * 2);
    const int prow = rowhalf * 8 + (lt >> 2);

    for (int kt = 0; kt < NTILES; ++kt) {
        const int cur = kt & 1;
        const uint32_t kvb = skv0 + (uint32_t)(cur * (KVBUF * 2));
        const bool hasNext = (kt + 1 < NTILES);

        if (hasNext && w == 0) gather(kt + 1);

        // ---- QK: warp tile [16h x 16t] over 144 dims (9 k-steps) ----
        float c[2][4];
        c[0][0]=c[0][1]=c[0][2]=c[0][3]=0.f;
        c[1][0]=c[1][1]=c[1][2]=c[1][3]=0.f;
        {
            uint32_t ka = kvb + qkB_off;
            #pragma unroll
            for (int s = 0; s < 9; ++s) {
                uint32_t b0, b1, b2, b3;
                ldsm_x4(b0, b1, b2, b3, ka); ka += 32;
                mma16816(c[0][0], c[0][1], c[0][2], c[0][3],
                         qf[4*s], qf[4*s+1], qf[4*s+2], qf[4*s+3], b0, b2,
                         c[0][0], c[0][1], c[0][2], c[0][3]);
                mma16816(c[1][0], c[1][1], c[1][2], c[1][3],
                         qf[4*s], qf[4*s+1], qf[4*s+2], qf[4*s+3], b1, b3,
                         c[1][0], c[1][1], c[1][2], c[1][3]);
            }
        }

        // export the 3 combos owned by partner warps (same nt group)
        // combo m = (rowhalf<<1 | ntile); values = c[m&1][(m>>1)*2], c[m&1][(m>>1)*2+1]
        #pragma unroll
        for (int m = 0; m < 4; ++m) {
            if (m != ks) {
                float* pb = sPart + (((nt * 4 + m) * 4 + ks) * 32 + lt) * 2;
                pb[0] = c[m & 1][(m >> 1) * 2];
                pb[1] = c[m & 1][(m >> 1) * 2 + 1];
            }
        }
        asm volatile("bar.sync %0, 128;" :: "r"(1 + nt) : "memory");   // B1 (per nt group)

        // ---- softmax (fixed base 0, log2 domain) on own combo ----
        {
            float s0 = c[ntile][rowhalf * 2];
            float s1 = c[ntile][rowhalf * 2 + 1];
            #pragma unroll
            for (int src = 0; src < 4; ++src) {
                if (src != ks) {
                    const float* pb = sPart + (((nt * 4 + ks) * 4 + src) * 32 + lt) * 2;
                    s0 += pb[0]; s1 += pb[1];
                }
            }
            int t0 = nt * 16 + ntile * 8 + (lt & 3) * 2;
            int i0 = sIdx[cur * 32 + t0];
            int i1 = sIdx[cur * 32 + t0 + 1];
            float p0 = (i0 < 0) ? 0.f : exp2f(s0);
            float p1 = (i1 < 0) ? 0.f : exp2f(s1);
            rs += p0 + p1;
            *(half2*)(sP + prow * PSTRIDE + t0) = __floats2half2_rn(p0, p1);
        }

        // pre-issue the first two PV V-tile loads (depend only on KV buf)
        uint32_t bbase = kvb + pvB_off;
        uint32_t vb0[4], vb1[4];
        ldsm_x4t(vb0[0], vb0[1], vb0[2], vb0[3], bbase);
        ldsm_x4t(vb1[0], vb1[1], vb1[2], vb1[3], bbase + 16u);

        __syncthreads();   // B2: all of P visible (PV reads both token halves)

        // ---- PV: warp tile [16h x 64d] = P[16x32] @ V[32x64] ----
        {
            uint32_t ap[2][4];
            #pragma unroll
            for (int k2 = 0; k2 < 2; ++k2) {
                uint32_t aa = spb + (uint32_t)(((lt & 15) * PSTRIDE + k2 * 16 + (lt >> 4) * 8) * 2);
                ldsm_x4(ap[k2][0], ap[k2][1], ap[k2][2], ap[k2][3], aa);
            }
            mma16816(accO[0][0], accO[0][1], accO[0][2], accO[0][3],
                     ap[0][0], ap[0][1], ap[0][2], ap[0][3], vb0[0], vb0[1],
                     accO[0][0], accO[0][1], accO[0][2], accO[0][3]);
            mma16816(accO[0][0], accO[0][1], accO[0][2], accO[0][3],
                     ap[1][0], ap[1][1], ap[1][2], ap[1][3], vb0[2], vb0[3],
                     accO[0][0], accO[0][1], accO[0][2], accO[0][3]);
            mma16816(accO[1][0], accO[1][1], accO[1][2], accO[1][3],
                     ap[0][0], ap[0][1], ap[0][2], ap[0][3], vb1[0], vb1[1],
                     accO[1][0], accO[1][1], accO[1][2], accO[1][3]);
            mma16816(accO[1][0], accO[1][1], accO[1][2], accO[1][3],
                     ap[1][0], ap[1][1], ap[1][2], ap[1][3], vb1[2], vb1[3],
                     accO[1][0], accO[1][1], accO[1][2], accO[1][3]);
            #pragma unroll
            for (int n2 = 2; n2 < 8; ++n2) {
                uint32_t b0, b1, b2, b3;
                ldsm_x4t(b0, b1, b2, b3, bbase + (uint32_t)(n2 * 16));
                mma16816(accO[n2][0], accO[n2][1], accO[n2][2], accO[n2][3],
                         ap[0][0], ap[0][1], ap[0][2], ap[0][3], b0, b1,
                         accO[n2][0], accO[n2][1], accO[n2][2], accO[n2][3]);
                mma16816(accO[n2][0], accO[n2][1], accO[n2][2], accO[n2][3],
                         ap[1][0], ap[1][1], ap[1][2], ap[1][3], b2, b3,
                         accO[n2][0], accO[n2][1], accO[n2][2], accO[n2][3]);
            }
        }

        if (hasNext && w == 0) MB_WAIT(mbar + (((kt + 1) & 1) * 8), ((kt + 1) >> 1) & 1);
        __syncthreads();   // B3: PV done everywhere; buffers rotate; TMA data visible
    }

    // ---- epilogue: reduce rs over the 4 lanes sharing a head row, export ----
    {
        rs += __shfl_xor_sync(0xffffffffu, rs, 1);
        rs += __shfl_xor_sync(0xffffffffu, rs, 2);
        if ((lt & 3) == 0) {
            int slot = nt * 2 + ntile;
            sLp[slot * 16 + prow] = rs;
        }
    }
    __syncthreads();

    {
        float* ob = out + ((size_t)tok * HH + hblk * HB) * DV;
        int r0 = lt >> 2;
        int r1 = r0 + 8;
        float d0 = sLp[r0] + sLp[16 + r0] + sLp[32 + r0] + sLp[48 + r0]
                 + __expf(sink[hblk * HB + r0]);
        float d1 = sLp[r1] + sLp[16 + r1] + sLp[32 + r1] + sLp[48 + r1]
                 + __expf(sink[hblk * HB + r1]);
        float rc0 = 1.0f / d0;
        float rc1 = 1.0f / d1;
        #pragma unroll
        for (int n2 = 0; n2 < 8; ++n2) {
            int d = w * 64 + n2 * 8 + (lt & 3) * 2;
            *(float2*)(ob + (size_t)r0 * DV + d) =
                make_float2(accO[n2][0] * rc0, accO[n2][1] * rc0);
            *(float2*)(ob + (size_t)r1 * DV + d) =
                make_float2(accO[n2][2] * rc1, accO[n2][3] * rc1);
        }
    }
}

extern "C" void kernel_launch(void* const* d_in, const int* in_sizes, int n_in,
                              void* d_out, int out_size)
{
    const float* q    = (const float*)d_in[0];
    const float* kv   = (const float*)d_in[1];
    const int*   topk = (const int*)d_in[2];
    const float* sink = (const float*)d_in[3];
    float*       out  = (float*)d_out;

    kv_to_half_kernel<<<(NKV * DD / 4) / 256, 256>>>(kv);

    cudaFuncSetAttribute(mla_v13_kernel,
                         cudaFuncAttributeMaxDynamicSharedMemorySize, SMEM_BYTES);

    dim3 grid(HH / HB, TT);   // (4, 512) = 2048 blocks
    dim3 block(256);
    mla_v13_kernel<<<grid, block, SMEM_BYTES>>>(q, topk, sink, out);
}